// round 11
// baseline (speedup 1.0000x reference)
#include <cuda_runtime.h>
#include <cuda_bf16.h>
#include <cuda_fp16.h>
#include <math.h>
#include <stdint.h>

#define N_NODES 50000
#define N_EDGES 800000
#define IN_F 256
#define H_F 128
#define N_CLS 16
#define NBLK ((N_NODES + 255) / 256)   // 196
#define NPW 8                          // nodes per warp in agg1

// ---------------- device scratch ----------------
__device__ int      g_deg_in[N_NODES];
__device__ int      g_deg_out[N_NODES];
__device__ int      g_row_off[N_NODES + 1];
__device__ int      g_blk_sum[NBLK];
__device__ int      g_slot[N_EDGES];
__device__ int      g_edge_src[N_EDGES];
__device__ float    g_norm_in[N_NODES];
__device__ float    g_norm_out[N_NODES];
__device__ __half   g_feat_h[N_NODES * IN_F];   // fp16 copy of feat
__device__ __half   g_w1h_t[H_F * IN_F];        // W1 transposed [c][k], fp16
__device__ __half   g_x1h[N_NODES * H_F];
__device__ float    g_x2[N_NODES * N_CLS];
__device__ unsigned g_bar_cnt;

// ---------------- conversions (no dependencies) ----------------
__global__ void feat2h_kernel(const float* __restrict__ feat) {
    int i = blockIdx.x * 256 + threadIdx.x;          // one float4 each
    if (i >= N_NODES * IN_F / 4) return;
    float4 f = reinterpret_cast<const float4*>(feat)[i];
    __half2 a = __floats2half2_rn(f.x, f.y);
    __half2 b = __floats2half2_rn(f.z, f.w);
    uint2 u;
    *reinterpret_cast<__half2*>(&u.x) = a;
    *reinterpret_cast<__half2*>(&u.y) = b;
    reinterpret_cast<uint2*>(g_feat_h)[i] = u;
}

__global__ void w1t_kernel(const float* __restrict__ W1) {
    int i = blockIdx.x * 256 + threadIdx.x;          // 32768
    if (i >= IN_F * H_F) return;
    int k = i >> 7, c = i & 127;
    g_w1h_t[c * IN_F + k] = __float2half_rn(W1[i]);
}

// ---------------- setup ----------------
__global__ void zero_kernel() {
    int i = blockIdx.x * blockDim.x + threadIdx.x;
    if (i < N_NODES) { g_deg_in[i] = 0; g_deg_out[i] = 0; }
}

__global__ void deg_kernel(const int* __restrict__ src, const int* __restrict__ dst) {
    int e = blockIdx.x * blockDim.x + threadIdx.x;
    if (e >= N_EDGES) return;
    atomicAdd(&g_deg_out[src[e]], 1);
    g_slot[e] = atomicAdd(&g_deg_in[dst[e]], 1);
}

__global__ void norm_kernel() {
    int i = blockIdx.x * blockDim.x + threadIdx.x;
    if (i >= N_NODES) return;
    int di = g_deg_in[i], dd = g_deg_out[i];
    g_norm_in[i]  = di > 0 ? rsqrtf((float)di) : 0.f;
    g_norm_out[i] = dd > 0 ? rsqrtf((float)dd) : 0.f;
}

__global__ void scan_kernel() {
    __shared__ int sw[8];
    __shared__ int s_carry;
    int b = blockIdx.x, t = threadIdx.x, lane = t & 31, wid = t >> 5;
    int i = b * 256 + t;

    int v = (i < N_NODES) ? g_deg_in[i] : 0;
    int s = v;
    #pragma unroll
    for (int o = 16; o > 0; o >>= 1) s += __shfl_xor_sync(0xffffffffu, s, o);
    if (lane == 0) sw[wid] = s;
    __syncthreads();
    if (t == 0) {
        int tot = 0;
        #pragma unroll
        for (int j = 0; j < 8; j++) tot += sw[j];
        g_blk_sum[b] = tot;
        __threadfence();
        unsigned old = atomicAdd(&g_bar_cnt, 1u);
        unsigned target = (old / NBLK + 1u) * NBLK;
        volatile unsigned* p = &g_bar_cnt;
        while (*p < target) { }
    }
    __syncthreads();
    __threadfence();

    int cv = (t < NBLK && t < b) ? g_blk_sum[t] : 0;
    #pragma unroll
    for (int o = 16; o > 0; o >>= 1) cv += __shfl_xor_sync(0xffffffffu, cv, o);
    __syncthreads();
    if (lane == 0) sw[wid] = cv;
    __syncthreads();
    if (t == 0) {
        int tot = 0;
        #pragma unroll
        for (int j = 0; j < 8; j++) tot += sw[j];
        s_carry = tot;
    }
    __syncthreads();
    int carry = s_carry;
    __syncthreads();

    int x = v;
    #pragma unroll
    for (int o = 1; o < 32; o <<= 1) {
        int y = __shfl_up_sync(0xffffffffu, x, o);
        if (lane >= o) x += y;
    }
    if (lane == 31) sw[wid] = x;
    __syncthreads();
    if (wid == 0 && lane < 8) {
        int ss = sw[lane];
        #pragma unroll
        for (int o = 1; o < 8; o <<= 1) {
            int y = __shfl_up_sync(0xffu, ss, o);
            if (lane >= o) ss += y;
        }
        sw[lane] = ss;
    }
    __syncthreads();
    int excl = carry + (wid ? sw[wid - 1] : 0) + x - v;
    if (i < N_NODES) g_row_off[i] = excl;
    if (i == N_NODES - 1) g_row_off[N_NODES] = excl + v;
}

__global__ void fill_kernel(const int* __restrict__ src, const int* __restrict__ dst) {
    int e = blockIdx.x * blockDim.x + threadIdx.x;
    if (e >= N_EDGES) return;
    g_edge_src[g_row_off[dst[e]] + g_slot[e]] = src[e];
}

// ---------------- GEMM1: fp16 m16n8k16 mma + cp.async ----------------
__device__ __forceinline__ void mma_f16(float* d, const uint32_t* a,
                                        uint32_t b0, uint32_t b1, const float* c) {
    asm volatile(
        "mma.sync.aligned.m16n8k16.row.col.f32.f16.f16.f32 "
        "{%0,%1,%2,%3}, {%4,%5,%6,%7}, {%8,%9}, {%10,%11,%12,%13};\n"
        : "=f"(d[0]), "=f"(d[1]), "=f"(d[2]), "=f"(d[3])
        : "r"(a[0]), "r"(a[1]), "r"(a[2]), "r"(a[3]),
          "r"(b0), "r"(b1),
          "f"(c[0]), "f"(c[1]), "f"(c[2]), "f"(c[3]));
}
__device__ __forceinline__ void cp16(uint32_t saddr, const void* gptr) {
    asm volatile("cp.async.cg.shared.global [%0], [%1], 16;\n" :: "r"(saddr), "l"(gptr));
}
__device__ __forceinline__ void cp_commit() {
    asm volatile("cp.async.commit_group;\n" ::: "memory");
}
__device__ __forceinline__ void cp_wait1() {
    asm volatile("cp.async.wait_group 1;\n" ::: "memory");
}

#define KC 64
#define AST 72                        // halves; conflict-free fragment LDS
#define ABUF (128 * AST)              // halves per buffer
#define GEMM1_SMEM (2 * (ABUF + ABUF) * 2)   // 73728 B

__global__ void __launch_bounds__(256) gemm1_kernel() {
    extern __shared__ __half smem_h[];
    __half* sA = smem_h;               // [2][ABUF]
    __half* sB = smem_h + 2 * ABUF;    // [2][ABUF]

    int t = threadIdx.x;
    int lane = t & 31, wid = t >> 5;
    int wm = wid >> 1, wn = wid & 1;   // warp tile: rows wm*32, cols wn*64
    int row0 = blockIdx.x * 128;
    int g = lane >> 2, tg = lane & 3;

    float acc[2][8][4];
    #pragma unroll
    for (int mt = 0; mt < 2; mt++)
        #pragma unroll
        for (int nt = 0; nt < 8; nt++)
            #pragma unroll
            for (int q = 0; q < 4; q++) acc[mt][nt][q] = 0.f;

    int prow[4], ppc[4], gr[4];
    uint32_t saA[4], saB[4];
    #pragma unroll
    for (int j = 0; j < 4; j++) {
        int idx = t + j * 256;         // 0..1023 = 128 rows × 8 pieces
        prow[j] = idx >> 3; ppc[j] = idx & 7;
        saA[j] = (uint32_t)__cvta_generic_to_shared(&sA[prow[j] * AST + ppc[j] * 8]);
        saB[j] = (uint32_t)__cvta_generic_to_shared(&sB[prow[j] * AST + ppc[j] * 8]);
        int grow = row0 + prow[j];
        gr[j] = grow < N_NODES ? grow : N_NODES - 1;
    }

    #pragma unroll
    for (int j = 0; j < 4; j++) {
        cp16(saA[j], g_feat_h + gr[j] * IN_F + ppc[j] * 8);
        cp16(saB[j], g_w1h_t + prow[j] * IN_F + ppc[j] * 8);
    }
    cp_commit();

    for (int kc = 0; kc < 4; kc++) {
        int cur = kc & 1;
        if (kc < 3) {
            uint32_t off = (uint32_t)((cur ^ 1) * ABUF * 2);
            #pragma unroll
            for (int j = 0; j < 4; j++) {
                cp16(saA[j] + off, g_feat_h + gr[j] * IN_F + (kc + 1) * KC + ppc[j] * 8);
                cp16(saB[j] + off, g_w1h_t + prow[j] * IN_F + (kc + 1) * KC + ppc[j] * 8);
            }
            cp_commit();
        } else {
            cp_commit();
        }
        cp_wait1();
        __syncthreads();

        __half* cA = sA + cur * ABUF;
        __half* cB = sB + cur * ABUF;
        #pragma unroll
        for (int ks = 0; ks < 4; ks++) {
            int k0 = ks * 16;
            uint32_t a[2][4];
            #pragma unroll
            for (int mt = 0; mt < 2; mt++) {
                int r = wm * 32 + mt * 16 + g;
                a[mt][0] = *reinterpret_cast<uint32_t*>(&cA[r * AST + k0 + 2 * tg]);
                a[mt][1] = *reinterpret_cast<uint32_t*>(&cA[(r + 8) * AST + k0 + 2 * tg]);
                a[mt][2] = *reinterpret_cast<uint32_t*>(&cA[r * AST + k0 + 8 + 2 * tg]);
                a[mt][3] = *reinterpret_cast<uint32_t*>(&cA[(r + 8) * AST + k0 + 8 + 2 * tg]);
            }
            #pragma unroll
            for (int nt = 0; nt < 8; nt++) {
                int n = wn * 64 + nt * 8 + g;
                uint32_t b0 = *reinterpret_cast<uint32_t*>(&cB[n * AST + k0 + 2 * tg]);
                uint32_t b1 = *reinterpret_cast<uint32_t*>(&cB[n * AST + k0 + 8 + 2 * tg]);
                mma_f16(acc[0][nt], a[0], b0, b1, acc[0][nt]);
                mma_f16(acc[1][nt], a[1], b0, b1, acc[1][nt]);
            }
        }
        __syncthreads();
    }

    #pragma unroll
    for (int mt = 0; mt < 2; mt++) {
        int r  = row0 + wm * 32 + mt * 16 + g;
        int r2 = r + 8;
        float no1 = (r  < N_NODES) ? g_norm_out[r]  : 0.f;
        float no2 = (r2 < N_NODES) ? g_norm_out[r2] : 0.f;
        #pragma unroll
        for (int nt = 0; nt < 8; nt++) {
            int col = wn * 64 + nt * 8 + tg * 2;
            if (r < N_NODES)
                *reinterpret_cast<__half2*>(&g_x1h[r * H_F + col]) =
                    __floats2half2_rn(acc[mt][nt][0] * no1, acc[mt][nt][1] * no1);
            if (r2 < N_NODES)
                *reinterpret_cast<__half2*>(&g_x1h[r2 * H_F + col]) =
                    __floats2half2_rn(acc[mt][nt][2] * no2, acc[mt][nt][3] * no2);
        }
    }
}

// ---------------- fused Agg1 + ReLU + GEMM2: 8 nodes per warp (R9 version) ----------------
__global__ void __launch_bounds__(256) agg1_gemm2_kernel(const float* __restrict__ b1,
                                                         const float* __restrict__ W2) {
    __shared__ float sWt[N_CLS * H_F];
    for (int i = threadIdx.x; i < H_F * N_CLS; i += 256) {
        int k = i >> 4, c = i & 15;
        sWt[c * H_F + k] = W2[i];
    }
    __syncthreads();

    int warp = threadIdx.x >> 5, lane = threadIdx.x & 31;
    int node0 = (blockIdx.x * 8 + warp) * NPW;
    const uint2* x1u = reinterpret_cast<const uint2*>(g_x1h);   // row stride 32
    float4 bb = reinterpret_cast<const float4*>(b1)[lane];

    #define ACC_U(u) do {                                               \
        float2 lo = __half22float2(*reinterpret_cast<__half2*>(&u.x));  \
        float2 hi = __half22float2(*reinterpret_cast<__half2*>(&u.y));  \
        accA.x += lo.x; accA.y += lo.y; accB.x += hi.x; accB.y += hi.y; \
    } while (0)
    #define ACC_EDGE(sv) do { uint2 u = x1u[(sv) * 32 + lane]; ACC_U(u); } while (0)
    #define BATCH(vv, dcur) do {                                                \
        int jj = 0;                                                             \
        for (; jj + 4 <= (dcur); jj += 4) {                                     \
            int t0 = __shfl_sync(0xffffffffu, vv, jj);                          \
            int t1 = __shfl_sync(0xffffffffu, vv, jj + 1);                      \
            int t2 = __shfl_sync(0xffffffffu, vv, jj + 2);                      \
            int t3 = __shfl_sync(0xffffffffu, vv, jj + 3);                      \
            uint2 u0 = x1u[t0 * 32 + lane];                                     \
            uint2 u1 = x1u[t1 * 32 + lane];                                     \
            uint2 u2 = x1u[t2 * 32 + lane];                                     \
            uint2 u3 = x1u[t3 * 32 + lane];                                     \
            ACC_U(u0); ACC_U(u1); ACC_U(u2); ACC_U(u3);                         \
        }                                                                       \
        for (; jj < (dcur); jj++) {                                             \
            int t0 = __shfl_sync(0xffffffffu, vv, jj);                          \
            ACC_EDGE(t0);                                                       \
        }                                                                       \
    } while (0)

    #pragma unroll 1
    for (int it = 0; it < NPW; it++) {
        int node = node0 + it;
        if (node >= N_NODES) break;
        int beg = g_row_off[node], end = g_row_off[node + 1];
        int deg = end - beg;

        int v0 = (beg + lane      < end) ? g_edge_src[beg + lane]      : 0;
        int v1 = (beg + 32 + lane < end) ? g_edge_src[beg + 32 + lane] : 0;

        float2 accA = make_float2(0.f, 0.f), accB = make_float2(0.f, 0.f);

        int d0 = deg < 32 ? deg : 32;
        BATCH(v0, d0);
        if (deg > 32) {
            int d1 = deg - 32; if (d1 > 32) d1 = 32;
            BATCH(v1, d1);
            for (int e = beg + 64; e < end; e++) ACC_EDGE(g_edge_src[e]);
        }

        float ni = g_norm_in[node], no = g_norm_out[node];
        float4 h;
        h.x = fmaxf(fmaf(accA.x, ni, bb.x), 0.f) * no;
        h.y = fmaxf(fmaf(accA.y, ni, bb.y), 0.f) * no;
        h.z = fmaxf(fmaf(accB.x, ni, bb.z), 0.f) * no;
        h.w = fmaxf(fmaf(accB.y, ni, bb.w), 0.f) * no;

        float p[N_CLS];
        #pragma unroll
        for (int c = 0; c < N_CLS; c++) {
            float4 w = reinterpret_cast<const float4*>(&sWt[c * H_F])[lane];
            p[c] = fmaf(h.x, w.x, fmaf(h.y, w.y, fmaf(h.z, w.z, h.w * w.w)));
        }
        #pragma unroll
        for (int o = 16; o > 0; o >>= 1) {
            #pragma unroll
            for (int c = 0; c < N_CLS; c++)
                p[c] += __shfl_xor_sync(0xffffffffu, p[c], o);
        }
        if (lane < N_CLS) g_x2[node * N_CLS + lane] = p[lane];
    }
    #undef BATCH
    #undef ACC_EDGE
    #undef ACC_U
}

// ---------------- Agg2 + bias + log_softmax ----------------
__global__ void __launch_bounds__(256) agg2_kernel(const float* __restrict__ b2,
                                                   float* __restrict__ out) {
    int node = blockIdx.x * 16 + (threadIdx.x >> 4);
    int c = threadIdx.x & 15;
    unsigned hm = 0xFFFFu << (((threadIdx.x >> 4) & 1) * 16);
    int beg = g_row_off[node], end = g_row_off[node + 1];
    int deg = end - beg;

    int v0 = (beg + c      < end) ? g_edge_src[beg + c]      : 0;
    int v1 = (beg + 16 + c < end) ? g_edge_src[beg + 16 + c] : 0;
    int v2 = (beg + 32 + c < end) ? g_edge_src[beg + 32 + c] : 0;
    int v3 = (beg + 48 + c < end) ? g_edge_src[beg + 48 + c] : 0;

    float acc = 0.f;
    int dcap = deg < 64 ? deg : 64;
    for (int j = 0; j < dcap; j++) {
        int w = j >> 4, jj = j & 15;
        int s = __shfl_sync(hm, w == 0 ? v0 : w == 1 ? v1 : w == 2 ? v2 : v3, jj, 16);
        acc += g_x2[s * N_CLS + c];
    }
    for (int e = beg + 64; e < end; e++)
        acc += g_x2[g_edge_src[e] * N_CLS + c];

    float v = fmaf(acc, g_norm_in[node], b2[c]);
    float m = v;
    #pragma unroll
    for (int o = 8; o > 0; o >>= 1)
        m = fmaxf(m, __shfl_xor_sync(hm, m, o, 16));
    float e = expf(v - m);
    float s = e;
    #pragma unroll
    for (int o = 8; o > 0; o >>= 1)
        s += __shfl_xor_sync(hm, s, o, 16);
    out[node * N_CLS + c] = v - m - logf(s);
}

// ---------------- launch (fork/join graph) ----------------
extern "C" void kernel_launch(void* const* d_in, const int* in_sizes, int n_in,
                              void* d_out, int out_size) {
    const float* feat = (const float*)d_in[0];
    const int*   src  = (const int*)  d_in[1];
    const int*   dst  = (const int*)  d_in[2];
    const float* W1   = (const float*)d_in[3];
    const float* b1   = (const float*)d_in[4];
    const float* W2   = (const float*)d_in[5];
    const float* b2   = (const float*)d_in[6];
    float* out = (float*)d_out;
    (void)in_sizes; (void)n_in; (void)out_size;

    static cudaStream_t s2 = nullptr;
    static cudaEvent_t evFork = nullptr, evNorm = nullptr, evJoin = nullptr;
    if (s2 == nullptr) {
        cudaStreamCreateWithFlags(&s2, cudaStreamNonBlocking);
        cudaEventCreateWithFlags(&evFork, cudaEventDisableTiming);
        cudaEventCreateWithFlags(&evNorm, cudaEventDisableTiming);
        cudaEventCreateWithFlags(&evJoin, cudaEventDisableTiming);
        cudaFuncSetAttribute(gemm1_kernel, cudaFuncAttributeMaxDynamicSharedMemorySize,
                             GEMM1_SMEM);
    }

    // fork immediately: conversions have no dependencies
    cudaEventRecord(evFork, 0);
    cudaStreamWaitEvent(s2, evFork, 0);
    feat2h_kernel<<<N_NODES * IN_F / 4 / 256, 256, 0, s2>>>(feat);
    w1t_kernel<<<(IN_F * H_F + 255) / 256, 256, 0, s2>>>(W1);

    // main: degrees + norms
    zero_kernel<<<(N_NODES + 255) / 256, 256>>>();
    deg_kernel<<<(N_EDGES + 255) / 256, 256>>>(src, dst);
    norm_kernel<<<(N_NODES + 255) / 256, 256>>>();

    // gemm1 (s2) needs norms; runs parallel to scan+fill
    cudaEventRecord(evNorm, 0);
    cudaStreamWaitEvent(s2, evNorm, 0);
    gemm1_kernel<<<(N_NODES + 127) / 128, 256, GEMM1_SMEM, s2>>>();
    scan_kernel<<<NBLK, 256>>>();
    fill_kernel<<<(N_EDGES + 255) / 256, 256>>>(src, dst);
    cudaEventRecord(evJoin, s2);
    cudaStreamWaitEvent(0, evJoin, 0);

    agg1_gemm2_kernel<<<(N_NODES + 8 * NPW * 8 - 1) / (8 * NPW), 256>>>(b1, W2);
    agg2_kernel<<<N_NODES / 16, 256>>>(b2, out);
}

// round 12
// speedup vs baseline: 1.0443x; 1.0443x over previous
#include <cuda_runtime.h>
#include <cuda_bf16.h>
#include <cuda_fp16.h>
#include <math.h>
#include <stdint.h>

#define N_NODES 50000
#define N_EDGES 800000
#define IN_F 256
#define H_F 128
#define N_CLS 16
#define NBLK ((N_NODES + 255) / 256)   // 196
#define NPW 8                          // nodes per warp in agg1

// ---------------- device scratch ----------------
__device__ int      g_deg_in[N_NODES];
__device__ int      g_deg_out[N_NODES];
__device__ int      g_row_off[N_NODES + 1];
__device__ int      g_blk_sum[NBLK];
__device__ int      g_slot[N_EDGES];
__device__ int      g_edge_src[N_EDGES];
__device__ float    g_norm_in[N_NODES];
__device__ float    g_norm_out[N_NODES];
__device__ float    g_x1f[N_NODES * H_F];    // raw feat @ W1 (fp32, unscaled)
__device__ __half   g_x1h[N_NODES * H_F];    // scaled fp16 version for agg1
__device__ float    g_x2[N_NODES * N_CLS];
__device__ unsigned g_bar_cnt;

// ---------------- setup ----------------
__global__ void zero_kernel() {
    int i = blockIdx.x * blockDim.x + threadIdx.x;
    if (i < N_NODES) { g_deg_in[i] = 0; g_deg_out[i] = 0; }
}

__global__ void deg_kernel(const int* __restrict__ src, const int* __restrict__ dst) {
    int e = blockIdx.x * blockDim.x + threadIdx.x;
    if (e >= N_EDGES) return;
    atomicAdd(&g_deg_out[src[e]], 1);
    g_slot[e] = atomicAdd(&g_deg_in[dst[e]], 1);
}

__global__ void norm_kernel() {
    int i = blockIdx.x * blockDim.x + threadIdx.x;
    if (i >= N_NODES) return;
    int di = g_deg_in[i], dd = g_deg_out[i];
    g_norm_in[i]  = di > 0 ? rsqrtf((float)di) : 0.f;
    g_norm_out[i] = dd > 0 ? rsqrtf((float)dd) : 0.f;
}

__global__ void scan_kernel() {
    __shared__ int sw[8];
    __shared__ int s_carry;
    int b = blockIdx.x, t = threadIdx.x, lane = t & 31, wid = t >> 5;
    int i = b * 256 + t;

    int v = (i < N_NODES) ? g_deg_in[i] : 0;
    int s = v;
    #pragma unroll
    for (int o = 16; o > 0; o >>= 1) s += __shfl_xor_sync(0xffffffffu, s, o);
    if (lane == 0) sw[wid] = s;
    __syncthreads();
    if (t == 0) {
        int tot = 0;
        #pragma unroll
        for (int j = 0; j < 8; j++) tot += sw[j];
        g_blk_sum[b] = tot;
        __threadfence();
        unsigned old = atomicAdd(&g_bar_cnt, 1u);
        unsigned target = (old / NBLK + 1u) * NBLK;
        volatile unsigned* p = &g_bar_cnt;
        while (*p < target) { }
    }
    __syncthreads();
    __threadfence();

    int cv = (t < NBLK && t < b) ? g_blk_sum[t] : 0;
    #pragma unroll
    for (int o = 16; o > 0; o >>= 1) cv += __shfl_xor_sync(0xffffffffu, cv, o);
    __syncthreads();
    if (lane == 0) sw[wid] = cv;
    __syncthreads();
    if (t == 0) {
        int tot = 0;
        #pragma unroll
        for (int j = 0; j < 8; j++) tot += sw[j];
        s_carry = tot;
    }
    __syncthreads();
    int carry = s_carry;
    __syncthreads();

    int x = v;
    #pragma unroll
    for (int o = 1; o < 32; o <<= 1) {
        int y = __shfl_up_sync(0xffffffffu, x, o);
        if (lane >= o) x += y;
    }
    if (lane == 31) sw[wid] = x;
    __syncthreads();
    if (wid == 0 && lane < 8) {
        int ss = sw[lane];
        #pragma unroll
        for (int o = 1; o < 8; o <<= 1) {
            int y = __shfl_up_sync(0xffu, ss, o);
            if (lane >= o) ss += y;
        }
        sw[lane] = ss;
    }
    __syncthreads();
    int excl = carry + (wid ? sw[wid - 1] : 0) + x - v;
    if (i < N_NODES) g_row_off[i] = excl;
    if (i == N_NODES - 1) g_row_off[N_NODES] = excl + v;
}

__global__ void fill_kernel(const int* __restrict__ src, const int* __restrict__ dst) {
    int e = blockIdx.x * blockDim.x + threadIdx.x;
    if (e >= N_EDGES) return;
    g_edge_src[g_row_off[dst[e]] + g_slot[e]] = src[e];
}

// ---------------- GEMM1 (tf32 mma + cp.async, fp32 inputs, UNSCALED output) ----------------
__device__ __forceinline__ void mma_tf32(float* d, const uint32_t* a, const uint32_t* b,
                                         const float* c) {
    asm volatile(
        "mma.sync.aligned.m16n8k8.row.col.f32.tf32.tf32.f32 "
        "{%0,%1,%2,%3}, {%4,%5,%6,%7}, {%8,%9}, {%10,%11,%12,%13};\n"
        : "=f"(d[0]), "=f"(d[1]), "=f"(d[2]), "=f"(d[3])
        : "r"(a[0]), "r"(a[1]), "r"(a[2]), "r"(a[3]),
          "r"(b[0]), "r"(b[1]),
          "f"(c[0]), "f"(c[1]), "f"(c[2]), "f"(c[3]));
}
__device__ __forceinline__ void cp16(uint32_t saddr, const void* gptr) {
    asm volatile("cp.async.cg.shared.global [%0], [%1], 16;\n" :: "r"(saddr), "l"(gptr));
}
__device__ __forceinline__ void cp_commit() {
    asm volatile("cp.async.commit_group;\n" ::: "memory");
}
__device__ __forceinline__ void cp_wait1() {
    asm volatile("cp.async.wait_group 1;\n" ::: "memory");
}

#define SA_STR 36
#define SB_STR 136
#define SA_WORDS (128 * SA_STR)
#define SB_WORDS (32 * SB_STR)
#define GEMM1_SMEM ((2 * (SA_WORDS + SB_WORDS)) * 4)

__global__ void __launch_bounds__(256) gemm1_kernel(const float* __restrict__ feat,
                                                    const float* __restrict__ W1) {
    extern __shared__ uint32_t smem[];
    uint32_t* sA = smem;
    uint32_t* sB = smem + 2 * SA_WORDS;

    int t = threadIdx.x;
    int lane = t & 31, wid = t >> 5;
    int wm = wid >> 1, wn = wid & 1;
    int row0 = blockIdx.x * 128;
    int g = lane >> 2, tg = lane & 3;

    float acc[2][8][4];
    #pragma unroll
    for (int mt = 0; mt < 2; mt++)
        #pragma unroll
        for (int nt = 0; nt < 8; nt++)
            #pragma unroll
            for (int q = 0; q < 4; q++) acc[mt][nt][q] = 0.f;

    const float4* feat4 = reinterpret_cast<const float4*>(feat);
    const float4* W14   = reinterpret_cast<const float4*>(W1);

    int ar[4], ac4[4], bkr[4], bc4[4];
    uint32_t saA[4], saB[4];
    #pragma unroll
    for (int j = 0; j < 4; j++) {
        int idx = t + j * 256;
        ar[j] = idx >> 3; ac4[j] = idx & 7;
        bkr[j] = idx >> 5; bc4[j] = idx & 31;
        saA[j] = (uint32_t)__cvta_generic_to_shared(&sA[ar[j] * SA_STR + ac4[j] * 4]);
        saB[j] = (uint32_t)__cvta_generic_to_shared(&sB[bkr[j] * SB_STR + bc4[j] * 4]);
    }
    int gr[4];
    #pragma unroll
    for (int j = 0; j < 4; j++) {
        int grow = row0 + ar[j];
        gr[j] = grow < N_NODES ? grow : N_NODES - 1;
    }

    #pragma unroll
    for (int j = 0; j < 4; j++) {
        cp16(saA[j], &feat4[gr[j] * 64 + ac4[j]]);
        cp16(saB[j], &W14[bkr[j] * 32 + bc4[j]]);
    }
    cp_commit();

    for (int kc = 0; kc < 8; kc++) {
        int cur = kc & 1;
        if (kc < 7) {
            int nxt = cur ^ 1;
            #pragma unroll
            for (int j = 0; j < 4; j++) {
                cp16(saA[j] + nxt * SA_WORDS * 4,
                     &feat4[gr[j] * 64 + (kc + 1) * 8 + ac4[j]]);
                cp16(saB[j] + nxt * SB_WORDS * 4,
                     &W14[((kc + 1) * 32 + bkr[j]) * 32 + bc4[j]]);
            }
            cp_commit();
        } else {
            cp_commit();
        }
        cp_wait1();
        __syncthreads();

        uint32_t* cA = &sA[cur * SA_WORDS];
        uint32_t* cB = &sB[cur * SB_WORDS];
        #pragma unroll
        for (int ks = 0; ks < 4; ks++) {
            int kk = ks * 8 + tg;
            uint32_t a[2][4];
            #pragma unroll
            for (int mt = 0; mt < 2; mt++) {
                int r = wm * 32 + mt * 16 + g;
                a[mt][0] = cA[r * SA_STR + kk];
                a[mt][1] = cA[(r + 8) * SA_STR + kk];
                a[mt][2] = cA[r * SA_STR + kk + 4];
                a[mt][3] = cA[(r + 8) * SA_STR + kk + 4];
            }
            #pragma unroll
            for (int nt = 0; nt < 8; nt++) {
                int col = wn * 64 + nt * 8 + g;
                uint32_t b[2];
                b[0] = cB[kk * SB_STR + col];
                b[1] = cB[(kk + 4) * SB_STR + col];
                mma_tf32(acc[0][nt], a[0], b, acc[0][nt]);
                mma_tf32(acc[1][nt], a[1], b, acc[1][nt]);
            }
        }
        __syncthreads();
    }

    // epilogue: raw fp32, no norm dependency
    #pragma unroll
    for (int mt = 0; mt < 2; mt++) {
        int r  = row0 + wm * 32 + mt * 16 + g;
        int r2 = r + 8;
        #pragma unroll
        for (int nt = 0; nt < 8; nt++) {
            int col = wn * 64 + nt * 8 + tg * 2;
            if (r < N_NODES)
                *reinterpret_cast<float2*>(&g_x1f[r * H_F + col]) =
                    make_float2(acc[mt][nt][0], acc[mt][nt][1]);
            if (r2 < N_NODES)
                *reinterpret_cast<float2*>(&g_x1f[r2 * H_F + col]) =
                    make_float2(acc[mt][nt][2], acc[mt][nt][3]);
        }
    }
}

// ---------------- scale + fp16 convert: x1h = half(x1f * norm_out[row]) ----------------
__global__ void __launch_bounds__(256) scale_kernel() {
    int i = blockIdx.x * 256 + threadIdx.x;      // one float4 -> half4
    if (i >= N_NODES * H_F / 4) return;
    int row = i >> 5;                            // H_F/4 = 32 float4 per row
    float n = g_norm_out[row];
    float4 f = reinterpret_cast<const float4*>(g_x1f)[i];
    uint2 u;
    *reinterpret_cast<__half2*>(&u.x) = __floats2half2_rn(f.x * n, f.y * n);
    *reinterpret_cast<__half2*>(&u.y) = __floats2half2_rn(f.z * n, f.w * n);
    reinterpret_cast<uint2*>(g_x1h)[i] = u;
}

// ---------------- fused Agg1 + ReLU + GEMM2: 8 nodes per warp (R9 version) ----------------
__global__ void __launch_bounds__(256) agg1_gemm2_kernel(const float* __restrict__ b1,
                                                         const float* __restrict__ W2) {
    __shared__ float sWt[N_CLS * H_F];
    for (int i = threadIdx.x; i < H_F * N_CLS; i += 256) {
        int k = i >> 4, c = i & 15;
        sWt[c * H_F + k] = W2[i];
    }
    __syncthreads();

    int warp = threadIdx.x >> 5, lane = threadIdx.x & 31;
    int node0 = (blockIdx.x * 8 + warp) * NPW;
    const uint2* x1u = reinterpret_cast<const uint2*>(g_x1h);   // row stride 32
    float4 bb = reinterpret_cast<const float4*>(b1)[lane];

    #define ACC_U(u) do {                                               \
        float2 lo = __half22float2(*reinterpret_cast<__half2*>(&u.x));  \
        float2 hi = __half22float2(*reinterpret_cast<__half2*>(&u.y));  \
        accA.x += lo.x; accA.y += lo.y; accB.x += hi.x; accB.y += hi.y; \
    } while (0)
    #define ACC_EDGE(sv) do { uint2 u = x1u[(sv) * 32 + lane]; ACC_U(u); } while (0)
    #define BATCH(vv, dcur) do {                                                \
        int jj = 0;                                                             \
        for (; jj + 4 <= (dcur); jj += 4) {                                     \
            int t0 = __shfl_sync(0xffffffffu, vv, jj);                          \
            int t1 = __shfl_sync(0xffffffffu, vv, jj + 1);                      \
            int t2 = __shfl_sync(0xffffffffu, vv, jj + 2);                      \
            int t3 = __shfl_sync(0xffffffffu, vv, jj + 3);                      \
            uint2 u0 = x1u[t0 * 32 + lane];                                     \
            uint2 u1 = x1u[t1 * 32 + lane];                                     \
            uint2 u2 = x1u[t2 * 32 + lane];                                     \
            uint2 u3 = x1u[t3 * 32 + lane];                                     \
            ACC_U(u0); ACC_U(u1); ACC_U(u2); ACC_U(u3);                         \
        }                                                                       \
        for (; jj < (dcur); jj++) {                                             \
            int t0 = __shfl_sync(0xffffffffu, vv, jj);                          \
            ACC_EDGE(t0);                                                       \
        }                                                                       \
    } while (0)

    #pragma unroll 1
    for (int it = 0; it < NPW; it++) {
        int node = node0 + it;
        if (node >= N_NODES) break;
        int beg = g_row_off[node], end = g_row_off[node + 1];
        int deg = end - beg;

        int v0 = (beg + lane      < end) ? g_edge_src[beg + lane]      : 0;
        int v1 = (beg + 32 + lane < end) ? g_edge_src[beg + 32 + lane] : 0;

        float2 accA = make_float2(0.f, 0.f), accB = make_float2(0.f, 0.f);

        int d0 = deg < 32 ? deg : 32;
        BATCH(v0, d0);
        if (deg > 32) {
            int d1 = deg - 32; if (d1 > 32) d1 = 32;
            BATCH(v1, d1);
            for (int e = beg + 64; e < end; e++) ACC_EDGE(g_edge_src[e]);
        }

        float ni = g_norm_in[node], no = g_norm_out[node];
        float4 h;
        h.x = fmaxf(fmaf(accA.x, ni, bb.x), 0.f) * no;
        h.y = fmaxf(fmaf(accA.y, ni, bb.y), 0.f) * no;
        h.z = fmaxf(fmaf(accB.x, ni, bb.z), 0.f) * no;
        h.w = fmaxf(fmaf(accB.y, ni, bb.w), 0.f) * no;

        float p[N_CLS];
        #pragma unroll
        for (int c = 0; c < N_CLS; c++) {
            float4 w = reinterpret_cast<const float4*>(&sWt[c * H_F])[lane];
            p[c] = fmaf(h.x, w.x, fmaf(h.y, w.y, fmaf(h.z, w.z, h.w * w.w)));
        }
        #pragma unroll
        for (int o = 16; o > 0; o >>= 1) {
            #pragma unroll
            for (int c = 0; c < N_CLS; c++)
                p[c] += __shfl_xor_sync(0xffffffffu, p[c], o);
        }
        if (lane < N_CLS) g_x2[node * N_CLS + lane] = p[lane];
    }
    #undef BATCH
    #undef ACC_EDGE
    #undef ACC_U
}

// ---------------- Agg2 + bias + log_softmax ----------------
__global__ void __launch_bounds__(256) agg2_kernel(const float* __restrict__ b2,
                                                   float* __restrict__ out) {
    int node = blockIdx.x * 16 + (threadIdx.x >> 4);
    int c = threadIdx.x & 15;
    unsigned hm = 0xFFFFu << (((threadIdx.x >> 4) & 1) * 16);
    int beg = g_row_off[node], end = g_row_off[node + 1];
    int deg = end - beg;

    int v0 = (beg + c      < end) ? g_edge_src[beg + c]      : 0;
    int v1 = (beg + 16 + c < end) ? g_edge_src[beg + 16 + c] : 0;
    int v2 = (beg + 32 + c < end) ? g_edge_src[beg + 32 + c] : 0;
    int v3 = (beg + 48 + c < end) ? g_edge_src[beg + 48 + c] : 0;

    float acc = 0.f;
    int dcap = deg < 64 ? deg : 64;
    for (int j = 0; j < dcap; j++) {
        int w = j >> 4, jj = j & 15;
        int s = __shfl_sync(hm, w == 0 ? v0 : w == 1 ? v1 : w == 2 ? v2 : v3, jj, 16);
        acc += g_x2[s * N_CLS + c];
    }
    for (int e = beg + 64; e < end; e++)
        acc += g_x2[g_edge_src[e] * N_CLS + c];

    float v = fmaf(acc, g_norm_in[node], b2[c]);
    float m = v;
    #pragma unroll
    for (int o = 8; o > 0; o >>= 1)
        m = fmaxf(m, __shfl_xor_sync(hm, m, o, 16));
    float e = expf(v - m);
    float s = e;
    #pragma unroll
    for (int o = 8; o > 0; o >>= 1)
        s += __shfl_xor_sync(hm, s, o, 16);
    out[node * N_CLS + c] = v - m - logf(s);
}

// ---------------- launch: gemm1 forks at t=0 ----------------
extern "C" void kernel_launch(void* const* d_in, const int* in_sizes, int n_in,
                              void* d_out, int out_size) {
    const float* feat = (const float*)d_in[0];
    const int*   src  = (const int*)  d_in[1];
    const int*   dst  = (const int*)  d_in[2];
    const float* W1   = (const float*)d_in[3];
    const float* b1   = (const float*)d_in[4];
    const float* W2   = (const float*)d_in[5];
    const float* b2   = (const float*)d_in[6];
    float* out = (float*)d_out;
    (void)in_sizes; (void)n_in; (void)out_size;

    static cudaStream_t s2 = nullptr;
    static cudaEvent_t evFork = nullptr, evNorm = nullptr, evJoin = nullptr;
    if (s2 == nullptr) {
        cudaStreamCreateWithFlags(&s2, cudaStreamNonBlocking);
        cudaEventCreateWithFlags(&evFork, cudaEventDisableTiming);
        cudaEventCreateWithFlags(&evNorm, cudaEventDisableTiming);
        cudaEventCreateWithFlags(&evJoin, cudaEventDisableTiming);
        cudaFuncSetAttribute(gemm1_kernel, cudaFuncAttributeMaxDynamicSharedMemorySize,
                             GEMM1_SMEM);
    }

    // fork at t=0: gemm1 has NO dependencies now (raw feat @ W1)
    cudaEventRecord(evFork, 0);
    cudaStreamWaitEvent(s2, evFork, 0);
    gemm1_kernel<<<(N_NODES + 127) / 128, 256, GEMM1_SMEM, s2>>>(feat, W1);

    // main stream: full CSR chain
    zero_kernel<<<(N_NODES + 255) / 256, 256>>>();
    deg_kernel<<<(N_EDGES + 255) / 256, 256>>>(src, dst);
    norm_kernel<<<(N_NODES + 255) / 256, 256>>>();
    cudaEventRecord(evNorm, 0);

    // scale pass on s2: needs gemm1 (program order on s2) + norms (event)
    cudaStreamWaitEvent(s2, evNorm, 0);
    scale_kernel<<<(N_NODES * H_F / 4 + 255) / 256, 256, 0, s2>>>();

    scan_kernel<<<NBLK, 256>>>();
    fill_kernel<<<(N_EDGES + 255) / 256, 256>>>(src, dst);

    cudaEventRecord(evJoin, s2);
    cudaStreamWaitEvent(0, evJoin, 0);

    agg1_gemm2_kernel<<<(N_NODES + 8 * NPW * 8 - 1) / (8 * NPW), 256>>>(b1, W2);
    agg2_kernel<<<N_NODES / 16, 256>>>(b2, out);
}

// round 14
// speedup vs baseline: 1.2531x; 1.2000x over previous
#include <cuda_runtime.h>
#include <cuda_bf16.h>
#include <cuda_fp16.h>
#include <math.h>
#include <stdint.h>

#define N_NODES 50000
#define N_EDGES 800000
#define IN_F 256
#define H_F 128
#define N_CLS 16
#define NBLK ((N_NODES + 255) / 256)   // 196
#define NPW 8                          // nodes per warp in agg1

// ---------------- device scratch ----------------
__device__ int      g_deg_in[N_NODES];
__device__ int      g_deg_out[N_NODES];
__device__ int      g_row_off[N_NODES + 1];
__device__ int      g_blk_sum[NBLK];
__device__ int      g_slot[N_EDGES];
__device__ int      g_edge_src[N_EDGES];
__device__ float    g_norm_in[N_NODES];
__device__ float    g_norm_out[N_NODES];
__device__ float    g_x1f[N_NODES * H_F];    // raw feat @ W1 (fp32, unscaled)
__device__ __half   g_x1h[N_NODES * H_F];    // scaled fp16 version for agg1
__device__ float    g_x2[N_NODES * N_CLS];
__device__ unsigned g_bar_cnt;

// ---------------- setup ----------------
__global__ void zero_kernel() {
    int i = blockIdx.x * blockDim.x + threadIdx.x;
    if (i < N_NODES) { g_deg_in[i] = 0; g_deg_out[i] = 0; }
}

__global__ void deg_kernel(const int* __restrict__ src, const int* __restrict__ dst) {
    int e = blockIdx.x * blockDim.x + threadIdx.x;
    if (e >= N_EDGES) return;
    atomicAdd(&g_deg_out[src[e]], 1);
    g_slot[e] = atomicAdd(&g_deg_in[dst[e]], 1);
}

__global__ void norm_kernel() {
    int i = blockIdx.x * blockDim.x + threadIdx.x;
    if (i >= N_NODES) return;
    int di = g_deg_in[i], dd = g_deg_out[i];
    g_norm_in[i]  = di > 0 ? rsqrtf((float)di) : 0.f;
    g_norm_out[i] = dd > 0 ? rsqrtf((float)dd) : 0.f;
}

__global__ void scan_kernel() {
    __shared__ int sw[8];
    __shared__ int s_carry;
    int b = blockIdx.x, t = threadIdx.x, lane = t & 31, wid = t >> 5;
    int i = b * 256 + t;

    int v = (i < N_NODES) ? g_deg_in[i] : 0;
    int s = v;
    #pragma unroll
    for (int o = 16; o > 0; o >>= 1) s += __shfl_xor_sync(0xffffffffu, s, o);
    if (lane == 0) sw[wid] = s;
    __syncthreads();
    if (t == 0) {
        int tot = 0;
        #pragma unroll
        for (int j = 0; j < 8; j++) tot += sw[j];
        g_blk_sum[b] = tot;
        __threadfence();
        unsigned old = atomicAdd(&g_bar_cnt, 1u);
        unsigned target = (old / NBLK + 1u) * NBLK;
        volatile unsigned* p = &g_bar_cnt;
        while (*p < target) { }
    }
    __syncthreads();
    __threadfence();

    int cv = (t < NBLK && t < b) ? g_blk_sum[t] : 0;
    #pragma unroll
    for (int o = 16; o > 0; o >>= 1) cv += __shfl_xor_sync(0xffffffffu, cv, o);
    __syncthreads();
    if (lane == 0) sw[wid] = cv;
    __syncthreads();
    if (t == 0) {
        int tot = 0;
        #pragma unroll
        for (int j = 0; j < 8; j++) tot += sw[j];
        s_carry = tot;
    }
    __syncthreads();
    int carry = s_carry;
    __syncthreads();

    int x = v;
    #pragma unroll
    for (int o = 1; o < 32; o <<= 1) {
        int y = __shfl_up_sync(0xffffffffu, x, o);
        if (lane >= o) x += y;
    }
    if (lane == 31) sw[wid] = x;
    __syncthreads();
    if (wid == 0 && lane < 8) {
        int ss = sw[lane];
        #pragma unroll
        for (int o = 1; o < 8; o <<= 1) {
            int y = __shfl_up_sync(0xffu, ss, o);
            if (lane >= o) ss += y;
        }
        sw[lane] = ss;
    }
    __syncthreads();
    int excl = carry + (wid ? sw[wid - 1] : 0) + x - v;
    if (i < N_NODES) g_row_off[i] = excl;
    if (i == N_NODES - 1) g_row_off[N_NODES] = excl + v;
}

__global__ void fill_kernel(const int* __restrict__ src, const int* __restrict__ dst) {
    int e = blockIdx.x * blockDim.x + threadIdx.x;
    if (e >= N_EDGES) return;
    g_edge_src[g_row_off[dst[e]] + g_slot[e]] = src[e];
}

// ---------------- GEMM1 (tf32 mma + cp.async, UNSCALED output) ----------------
__device__ __forceinline__ void mma_tf32(float* d, const uint32_t* a, const uint32_t* b,
                                         const float* c) {
    asm volatile(
        "mma.sync.aligned.m16n8k8.row.col.f32.tf32.tf32.f32 "
        "{%0,%1,%2,%3}, {%4,%5,%6,%7}, {%8,%9}, {%10,%11,%12,%13};\n"
        : "=f"(d[0]), "=f"(d[1]), "=f"(d[2]), "=f"(d[3])
        : "r"(a[0]), "r"(a[1]), "r"(a[2]), "r"(a[3]),
          "r"(b[0]), "r"(b[1]),
          "f"(c[0]), "f"(c[1]), "f"(c[2]), "f"(c[3]));
}
__device__ __forceinline__ void mma_f16(float* d, const uint32_t* a,
                                        uint32_t b0, uint32_t b1, const float* c) {
    asm volatile(
        "mma.sync.aligned.m16n8k16.row.col.f32.f16.f16.f32 "
        "{%0,%1,%2,%3}, {%4,%5,%6,%7}, {%8,%9}, {%10,%11,%12,%13};\n"
        : "=f"(d[0]), "=f"(d[1]), "=f"(d[2]), "=f"(d[3])
        : "r"(a[0]), "r"(a[1]), "r"(a[2]), "r"(a[3]),
          "r"(b0), "r"(b1),
          "f"(c[0]), "f"(c[1]), "f"(c[2]), "f"(c[3]));
}
__device__ __forceinline__ void cp16(uint32_t saddr, const void* gptr) {
    asm volatile("cp.async.cg.shared.global [%0], [%1], 16;\n" :: "r"(saddr), "l"(gptr));
}
__device__ __forceinline__ void cp_commit() {
    asm volatile("cp.async.commit_group;\n" ::: "memory");
}
__device__ __forceinline__ void cp_wait1() {
    asm volatile("cp.async.wait_group 1;\n" ::: "memory");
}

#define SA_STR 36
#define SB_STR 136
#define SA_WORDS (128 * SA_STR)
#define SB_WORDS (32 * SB_STR)
#define GEMM1_SMEM ((2 * (SA_WORDS + SB_WORDS)) * 4)

__global__ void __launch_bounds__(256) gemm1_kernel(const float* __restrict__ feat,
                                                    const float* __restrict__ W1) {
    extern __shared__ uint32_t smem[];
    uint32_t* sA = smem;
    uint32_t* sB = smem + 2 * SA_WORDS;

    int t = threadIdx.x;
    int lane = t & 31, wid = t >> 5;
    int wm = wid >> 1, wn = wid & 1;
    int row0 = blockIdx.x * 128;
    int g = lane >> 2, tg = lane & 3;

    float acc[2][8][4];
    #pragma unroll
    for (int mt = 0; mt < 2; mt++)
        #pragma unroll
        for (int nt = 0; nt < 8; nt++)
            #pragma unroll
            for (int q = 0; q < 4; q++) acc[mt][nt][q] = 0.f;

    const float4* feat4 = reinterpret_cast<const float4*>(feat);
    const float4* W14   = reinterpret_cast<const float4*>(W1);

    int ar[4], ac4[4], bkr[4], bc4[4];
    uint32_t saA[4], saB[4];
    #pragma unroll
    for (int j = 0; j < 4; j++) {
        int idx = t + j * 256;
        ar[j] = idx >> 3; ac4[j] = idx & 7;
        bkr[j] = idx >> 5; bc4[j] = idx & 31;
        saA[j] = (uint32_t)__cvta_generic_to_shared(&sA[ar[j] * SA_STR + ac4[j] * 4]);
        saB[j] = (uint32_t)__cvta_generic_to_shared(&sB[bkr[j] * SB_STR + bc4[j] * 4]);
    }
    int gr[4];
    #pragma unroll
    for (int j = 0; j < 4; j++) {
        int grow = row0 + ar[j];
        gr[j] = grow < N_NODES ? grow : N_NODES - 1;
    }

    #pragma unroll
    for (int j = 0; j < 4; j++) {
        cp16(saA[j], &feat4[gr[j] * 64 + ac4[j]]);
        cp16(saB[j], &W14[bkr[j] * 32 + bc4[j]]);
    }
    cp_commit();

    for (int kc = 0; kc < 8; kc++) {
        int cur = kc & 1;
        if (kc < 7) {
            int nxt = cur ^ 1;
            #pragma unroll
            for (int j = 0; j < 4; j++) {
                cp16(saA[j] + nxt * SA_WORDS * 4,
                     &feat4[gr[j] * 64 + (kc + 1) * 8 + ac4[j]]);
                cp16(saB[j] + nxt * SB_WORDS * 4,
                     &W14[((kc + 1) * 32 + bkr[j]) * 32 + bc4[j]]);
            }
            cp_commit();
        } else {
            cp_commit();
        }
        cp_wait1();
        __syncthreads();

        uint32_t* cA = &sA[cur * SA_WORDS];
        uint32_t* cB = &sB[cur * SB_WORDS];
        #pragma unroll
        for (int ks = 0; ks < 4; ks++) {
            int kk = ks * 8 + tg;
            uint32_t a[2][4];
            #pragma unroll
            for (int mt = 0; mt < 2; mt++) {
                int r = wm * 32 + mt * 16 + g;
                a[mt][0] = cA[r * SA_STR + kk];
                a[mt][1] = cA[(r + 8) * SA_STR + kk];
                a[mt][2] = cA[r * SA_STR + kk + 4];
                a[mt][3] = cA[(r + 8) * SA_STR + kk + 4];
            }
            #pragma unroll
            for (int nt = 0; nt < 8; nt++) {
                int col = wn * 64 + nt * 8 + g;
                uint32_t b[2];
                b[0] = cB[kk * SB_STR + col];
                b[1] = cB[(kk + 4) * SB_STR + col];
                mma_tf32(acc[0][nt], a[0], b, acc[0][nt]);
                mma_tf32(acc[1][nt], a[1], b, acc[1][nt]);
            }
        }
        __syncthreads();
    }

    #pragma unroll
    for (int mt = 0; mt < 2; mt++) {
        int r  = row0 + wm * 32 + mt * 16 + g;
        int r2 = r + 8;
        #pragma unroll
        for (int nt = 0; nt < 8; nt++) {
            int col = wn * 64 + nt * 8 + tg * 2;
            if (r < N_NODES)
                *reinterpret_cast<float2*>(&g_x1f[r * H_F + col]) =
                    make_float2(acc[mt][nt][0], acc[mt][nt][1]);
            if (r2 < N_NODES)
                *reinterpret_cast<float2*>(&g_x1f[r2 * H_F + col]) =
                    make_float2(acc[mt][nt][2], acc[mt][nt][3]);
        }
    }
}

// ---------------- scale + fp16 convert ----------------
__global__ void __launch_bounds__(256) scale_kernel() {
    int i = blockIdx.x * 256 + threadIdx.x;
    if (i >= N_NODES * H_F / 4) return;
    int row = i >> 5;
    float n = g_norm_out[row];
    float4 f = reinterpret_cast<const float4*>(g_x1f)[i];
    uint2 u;
    *reinterpret_cast<__half2*>(&u.x) = __floats2half2_rn(f.x * n, f.y * n);
    *reinterpret_cast<__half2*>(&u.y) = __floats2half2_rn(f.z * n, f.w * n);
    reinterpret_cast<uint2*>(g_x1h)[i] = u;
}

// ---------------- fused Agg1 + ReLU + tensor-core GEMM2 ----------------
// CTA = 8 warps x 8 nodes = 64 nodes.
// Phase 1: warp gathers per node, h -> fp16 smem.
// Phase 2: warps 0-3 compute x2[64x16] = h @ W2 via m16n8k16.
// HST = 136 halves (128 data + 8 pad): word-stride 68 => bank (4g+tg)%32,
// all 32 lanes distinct for fragment LDS. (R13 bug: HST=72 < 128 data -> OOB.)
#define HST 136

__global__ void __launch_bounds__(256) agg1_gemm2_kernel(const float* __restrict__ b1,
                                                         const float* __restrict__ W2) {
    __shared__ __half sH[64 * HST];      // 17408 B
    __shared__ __half sW[16 * HST];      // 4352 B

    int t = threadIdx.x;
    int warp = t >> 5, lane = t & 31;
    int g = lane >> 2, tg = lane & 3;
    int node0 = blockIdx.x * 64;

    // stage W2^T (fp16): sW[c][k]
    for (int i = t; i < H_F * N_CLS; i += 256) {
        int k = i >> 4, c = i & 15;
        sW[c * HST + k] = __float2half_rn(W2[i]);
    }

    const uint2* x1u = reinterpret_cast<const uint2*>(g_x1h);   // row stride 32
    float4 bb = reinterpret_cast<const float4*>(b1)[lane];

    #define ACC_U(u) do {                                               \
        float2 lo = __half22float2(*reinterpret_cast<__half2*>(&u.x));  \
        float2 hi = __half22float2(*reinterpret_cast<__half2*>(&u.y));  \
        accA.x += lo.x; accA.y += lo.y; accB.x += hi.x; accB.y += hi.y; \
    } while (0)
    #define ACC_EDGE(sv) do { uint2 u = x1u[(sv) * 32 + lane]; ACC_U(u); } while (0)
    #define BATCH(vv, dcur) do {                                                \
        int jj = 0;                                                             \
        for (; jj + 4 <= (dcur); jj += 4) {                                     \
            int t0 = __shfl_sync(0xffffffffu, vv, jj);                          \
            int t1 = __shfl_sync(0xffffffffu, vv, jj + 1);                      \
            int t2 = __shfl_sync(0xffffffffu, vv, jj + 2);                      \
            int t3 = __shfl_sync(0xffffffffu, vv, jj + 3);                      \
            uint2 u0 = x1u[t0 * 32 + lane];                                     \
            uint2 u1 = x1u[t1 * 32 + lane];                                     \
            uint2 u2 = x1u[t2 * 32 + lane];                                     \
            uint2 u3 = x1u[t3 * 32 + lane];                                     \
            ACC_U(u0); ACC_U(u1); ACC_U(u2); ACC_U(u3);                         \
        }                                                                       \
        for (; jj < (dcur); jj++) {                                             \
            int t0 = __shfl_sync(0xffffffffu, vv, jj);                          \
            ACC_EDGE(t0);                                                       \
        }                                                                       \
    } while (0)

    // Phase 1: 8 nodes per warp; h -> smem fp16
    #pragma unroll 1
    for (int it = 0; it < NPW; it++) {
        int ln = warp * NPW + it;            // local node 0..63
        int node = node0 + ln;
        float2 accA = make_float2(0.f, 0.f), accB = make_float2(0.f, 0.f);
        float ni = 0.f, no = 0.f;
        if (node < N_NODES) {
            int beg = g_row_off[node], end = g_row_off[node + 1];
            int deg = end - beg;
            int v0 = (beg + lane      < end) ? g_edge_src[beg + lane]      : 0;
            int v1 = (beg + 32 + lane < end) ? g_edge_src[beg + 32 + lane] : 0;
            int d0 = deg < 32 ? deg : 32;
            BATCH(v0, d0);
            if (deg > 32) {
                int d1 = deg - 32; if (d1 > 32) d1 = 32;
                BATCH(v1, d1);
                for (int e = beg + 64; e < end; e++) ACC_EDGE(g_edge_src[e]);
            }
            ni = g_norm_in[node]; no = g_norm_out[node];
        }
        float hx = fmaxf(fmaf(accA.x, ni, bb.x), 0.f) * no;
        float hy = fmaxf(fmaf(accA.y, ni, bb.y), 0.f) * no;
        float hz = fmaxf(fmaf(accB.x, ni, bb.z), 0.f) * no;
        float hw = fmaxf(fmaf(accB.y, ni, bb.w), 0.f) * no;
        if (node >= N_NODES) { hx = hy = hz = hw = 0.f; }
        __half2* dstp = reinterpret_cast<__half2*>(&sH[ln * HST + lane * 4]);
        dstp[0] = __floats2half2_rn(hx, hy);
        dstp[1] = __floats2half2_rn(hz, hw);
    }
    #undef BATCH
    #undef ACC_EDGE
    #undef ACC_U

    __syncthreads();

    // Phase 2: warps 0-3: x2[16x16 tile] = h_tile @ W2
    if (warp < 4) {
        float acc[2][4];
        #pragma unroll
        for (int nh = 0; nh < 2; nh++)
            #pragma unroll
            for (int q = 0; q < 4; q++) acc[nh][q] = 0.f;

        #pragma unroll
        for (int ks = 0; ks < 8; ks++) {
            int k0 = ks * 16;
            int r = warp * 16 + g;
            uint32_t a[4];
            a[0] = *reinterpret_cast<uint32_t*>(&sH[r * HST + k0 + 2 * tg]);
            a[1] = *reinterpret_cast<uint32_t*>(&sH[(r + 8) * HST + k0 + 2 * tg]);
            a[2] = *reinterpret_cast<uint32_t*>(&sH[r * HST + k0 + 8 + 2 * tg]);
            a[3] = *reinterpret_cast<uint32_t*>(&sH[(r + 8) * HST + k0 + 8 + 2 * tg]);
            #pragma unroll
            for (int nh = 0; nh < 2; nh++) {
                int n = nh * 8 + g;
                uint32_t b0 = *reinterpret_cast<uint32_t*>(&sW[n * HST + k0 + 2 * tg]);
                uint32_t b1 = *reinterpret_cast<uint32_t*>(&sW[n * HST + k0 + 8 + 2 * tg]);
                mma_f16(acc[nh], a, b0, b1, acc[nh]);
            }
        }

        int r  = node0 + warp * 16 + g;
        int r2 = r + 8;
        #pragma unroll
        for (int nh = 0; nh < 2; nh++) {
            int c = nh * 8 + tg * 2;
            if (r < N_NODES)
                *reinterpret_cast<float2*>(&g_x2[r * N_CLS + c]) =
                    make_float2(acc[nh][0], acc[nh][1]);
            if (r2 < N_NODES)
                *reinterpret_cast<float2*>(&g_x2[r2 * N_CLS + c]) =
                    make_float2(acc[nh][2], acc[nh][3]);
        }
    }
}

// ---------------- Agg2 + bias + log_softmax ----------------
__global__ void __launch_bounds__(256) agg2_kernel(const float* __restrict__ b2,
                                                   float* __restrict__ out) {
    int node = blockIdx.x * 16 + (threadIdx.x >> 4);
    int c = threadIdx.x & 15;
    unsigned hm = 0xFFFFu << (((threadIdx.x >> 4) & 1) * 16);
    int beg = g_row_off[node], end = g_row_off[node + 1];
    int deg = end - beg;

    int v0 = (beg + c      < end) ? g_edge_src[beg + c]      : 0;
    int v1 = (beg + 16 + c < end) ? g_edge_src[beg + 16 + c] : 0;
    int v2 = (beg + 32 + c < end) ? g_edge_src[beg + 32 + c] : 0;
    int v3 = (beg + 48 + c < end) ? g_edge_src[beg + 48 + c] : 0;

    float acc = 0.f;
    int dcap = deg < 64 ? deg : 64;
    for (int j = 0; j < dcap; j++) {
        int w = j >> 4, jj = j & 15;
        int s = __shfl_sync(hm, w == 0 ? v0 : w == 1 ? v1 : w == 2 ? v2 : v3, jj, 16);
        acc += g_x2[s * N_CLS + c];
    }
    for (int e = beg + 64; e < end; e++)
        acc += g_x2[g_edge_src[e] * N_CLS + c];

    float v = fmaf(acc, g_norm_in[node], b2[c]);
    float m = v;
    #pragma unroll
    for (int o = 8; o > 0; o >>= 1)
        m = fmaxf(m, __shfl_xor_sync(hm, m, o, 16));
    float e = expf(v - m);
    float s = e;
    #pragma unroll
    for (int o = 8; o > 0; o >>= 1)
        s += __shfl_xor_sync(hm, s, o, 16);
    out[node * N_CLS + c] = v - m - logf(s);
}

// ---------------- launch ----------------
extern "C" void kernel_launch(void* const* d_in, const int* in_sizes, int n_in,
                              void* d_out, int out_size) {
    const float* feat = (const float*)d_in[0];
    const int*   src  = (const int*)  d_in[1];
    const int*   dst  = (const int*)  d_in[2];
    const float* W1   = (const float*)d_in[3];
    const float* b1   = (const float*)d_in[4];
    const float* W2   = (const float*)d_in[5];
    const float* b2   = (const float*)d_in[6];
    float* out = (float*)d_out;
    (void)in_sizes; (void)n_in; (void)out_size;

    static cudaStream_t s2 = nullptr;
    static cudaEvent_t evFork = nullptr, evNorm = nullptr, evJoin = nullptr;
    if (s2 == nullptr) {
        cudaStreamCreateWithFlags(&s2, cudaStreamNonBlocking);
        cudaEventCreateWithFlags(&evFork, cudaEventDisableTiming);
        cudaEventCreateWithFlags(&evNorm, cudaEventDisableTiming);
        cudaEventCreateWithFlags(&evJoin, cudaEventDisableTiming);
        cudaFuncSetAttribute(gemm1_kernel, cudaFuncAttributeMaxDynamicSharedMemorySize,
                             GEMM1_SMEM);
    }

    // fork at t=0: gemm1 has no dependencies (raw feat @ W1)
    cudaEventRecord(evFork, 0);
    cudaStreamWaitEvent(s2, evFork, 0);
    gemm1_kernel<<<(N_NODES + 127) / 128, 256, GEMM1_SMEM, s2>>>(feat, W1);

    // main stream: CSR chain
    zero_kernel<<<(N_NODES + 255) / 256, 256>>>();
    deg_kernel<<<(N_EDGES + 255) / 256, 256>>>(src, dst);
    norm_kernel<<<(N_NODES + 255) / 256, 256>>>();
    cudaEventRecord(evNorm, 0);

    cudaStreamWaitEvent(s2, evNorm, 0);
    scale_kernel<<<(N_NODES * H_F / 4 + 255) / 256, 256, 0, s2>>>();

    scan_kernel<<<NBLK, 256>>>();
    fill_kernel<<<(N_EDGES + 255) / 256, 256>>>(src, dst);

    cudaEventRecord(evJoin, s2);
    cudaStreamWaitEvent(0, evJoin, 0);

    agg1_gemm2_kernel<<<(N_NODES + 63) / 64, 256>>>(b1, W2);
    agg2_kernel<<<N_NODES / 16, 256>>>(b2, out);
}